// round 2
// baseline (speedup 1.0000x reference)
#include <cuda_runtime.h>

#define T_STEPS 65536
#define INPUT   99
#define HIDDEN  64
#define GATES   256   // 4*HIDDEN
#define TS      16    // timesteps per block in the precompute kernel

// Precomputed input projections, permuted so scan-thread j reads
// g_xz[t*256 + j] (coalesced). Thread j = 4*u + q owns gate row
// r = qmap[q]*64 + u with qmap = {0,2,1,3}  (lane q: 0->i, 1->g, 2->f, 3->o).
// +8 steps of padding so the prefetch ring can read past the end harmlessly.
__device__ float g_xz[(T_STEPS + 8) * GATES];

typedef unsigned long long ull;

// ---------------- packed f32x2 helpers (Blackwell double-rate fp32) ----------------
__device__ __forceinline__ ull fma2(ull a, ull b, ull c) {
    ull d;
    asm("fma.rn.f32x2 %0, %1, %2, %3;" : "=l"(d) : "l"(a), "l"(b), "l"(c));
    return d;
}
__device__ __forceinline__ ull add2(ull a, ull b) {
    ull d;
    asm("add.rn.f32x2 %0, %1, %2;" : "=l"(d) : "l"(a), "l"(b));
    return d;
}
__device__ __forceinline__ ull pack2(float lo, float hi) {
    ull r;
    asm("mov.b64 %0, {%1, %2};" : "=l"(r) : "f"(lo), "f"(hi));
    return r;
}
__device__ __forceinline__ float lo32(ull v) { return __uint_as_float((unsigned)v); }
__device__ __forceinline__ float hi32(ull v) { return __uint_as_float((unsigned)(v >> 32)); }

// ---------------- fast-but-accurate transcendentals (MUFU, err ~1e-7) ----------------
__device__ __forceinline__ float fast_ex2(float x) {
    float y; asm("ex2.approx.f32 %0, %1;" : "=f"(y) : "f"(x)); return y;
}
__device__ __forceinline__ float fast_rcp(float x) {
    float y; asm("rcp.approx.f32 %0, %1;" : "=f"(y) : "f"(x)); return y;
}
__device__ __forceinline__ float sigmoidf_(float x) {
    return fast_rcp(1.0f + fast_ex2(-1.4426950408889634f * x));
}
__device__ __forceinline__ float tanhf_(float x) {
    // tanh(x) = 2*sigmoid(2x) - 1
    return fmaf(2.0f, fast_rcp(1.0f + fast_ex2(-2.8853900817779268f * x)), -1.0f);
}

// ============================================================================
// Kernel 1: xz[t][g] = sum_d x[t][d] * W_ih[g][d] + b_ih[g] + b_hh[g]
// Block = 256 threads (one per gate row), TS=16 timesteps per block.
// Scatters into the permuted layout the scan kernel wants.
// ============================================================================
__global__ void xz_kernel(const float* __restrict__ x,
                          const float* __restrict__ W_ih,
                          const float* __restrict__ b_ih,
                          const float* __restrict__ b_hh) {
    __shared__ __align__(16) float xs[INPUT * TS];  // [d][t]
    const int tid = threadIdx.x;
    const int t0  = blockIdx.x * TS;

    for (int i = tid; i < TS * INPUT; i += 256) {
        int t = i / INPUT;
        int d = i - t * INPUT;
        xs[d * TS + t] = x[(size_t)(t0 + t) * INPUT + d];
    }
    __syncthreads();

    const int g = tid;
    float bs = b_ih[g] + b_hh[g];
    float acc[TS];
#pragma unroll
    for (int t = 0; t < TS; t++) acc[t] = bs;

    const float* wrow = W_ih + g * INPUT;
#pragma unroll 3
    for (int d = 0; d < INPUT; d++) {
        float w = __ldg(wrow + d);
        const float4* xv = (const float4*)(xs + d * TS);
#pragma unroll
        for (int q = 0; q < TS / 4; q++) {
            float4 v = xv[q];
            acc[q * 4 + 0] = fmaf(w, v.x, acc[q * 4 + 0]);
            acc[q * 4 + 1] = fmaf(w, v.y, acc[q * 4 + 1]);
            acc[q * 4 + 2] = fmaf(w, v.z, acc[q * 4 + 2]);
            acc[q * 4 + 3] = fmaf(w, v.w, acc[q * 4 + 3]);
        }
    }

    // Scatter: gate gi = g>>6, unit u = g&63 -> scan thread j = u*4 + qinv[gi]
    // qinv = {0,2,1,3} (i->lane0, f->lane2, g->lane1, o->lane3).
    const int u  = g & 63;
    const int gi = g >> 6;
    const int qinv = (gi == 0) ? 0 : (gi == 1) ? 2 : (gi == 2) ? 1 : 3;
    const int jj = u * 4 + qinv;
#pragma unroll
    for (int t = 0; t < TS; t++) {
        g_xz[(size_t)(t0 + t) * GATES + jj] = acc[t];
    }
}

// ============================================================================
// Kernel 2: persistent single-CTA LSTM scan + MLP head.
// 256 threads, 8 warps. Thread j = 4u+q owns one W_hh gate row in registers.
// Per step (ONE __syncthreads):
//   z = xz (prefetched, coalesced) + W_row @ h      (32 f32x2 FMAs)
//   v = nonlin(z)   lane q: 0->sig(i) 1->tanh(g) 2->sig(f) 3->sig(o)
//   bfly xor1: lane0 gets g, lane2 gets o
//   p = (q&2) ? f*c : i*g ; bfly xor2 ; c = p + y   (c valid in lanes 0,2)
//   lane2: h = o * tanh(c) -> double-buffered SMEM
// ============================================================================
__global__ void __launch_bounds__(256, 1)
scan_kernel(const float* __restrict__ Whh,
            const float* __restrict__ W1,
            const float* __restrict__ W2,
            const float* __restrict__ b2v,
            float* __restrict__ out) {
    __shared__ __align__(16) float hb[2][HIDDEN];  // double-buffered hidden state
    __shared__ float fo[32];                       // head scratch
    const int j = threadIdx.x;
    const int u = j >> 2;
    const int q = j & 3;

    // Gate row for this lane: qmap = {0,2,1,3}
    const int gi = (q == 0) ? 0 : (q == 1) ? 2 : (q == 2) ? 1 : 3;
    const int r  = gi * 64 + u;

    // W_hh row r as 32 packed f32x2 (rows 256B-aligned; pairs 8B-aligned).
    ull w[32];
    const ull* W64 = (const ull*)Whh;
#pragma unroll
    for (int i = 0; i < 32; i++) w[i] = W64[r * 32 + i];

    if (j < HIDDEN) hb[0][j] = 0.0f;
    float c = 0.0f;

    // Depth-8 register prefetch ring, coalesced (thread j reads column j).
    const float* xzp = g_xz + j;
    float ring[8];
#pragma unroll
    for (int p = 0; p < 8; p++) ring[p] = xzp[(size_t)p * GATES];
    __syncthreads();

    for (int t = 0; t < T_STEPS; t += 8) {
#pragma unroll
        for (int s = 0; s < 8; s++) {
            float xz = ring[s];
            ring[s] = xzp[(size_t)(t + s + 8) * GATES];  // <= T+7, padded

            // ---- matvec: z = xz + W_row @ h ----
            const ulonglong2* h64 = (const ulonglong2*)hb[(t + s) & 1];
            ull a0 = pack2(xz, 0.0f), a1 = 0, a2 = 0, a3 = 0;
#pragma unroll
            for (int kq = 0; kq < 8; kq++) {
                ulonglong2 hx = h64[kq * 2];
                ulonglong2 hy = h64[kq * 2 + 1];
                a0 = fma2(w[kq * 4 + 0], hx.x, a0);
                a1 = fma2(w[kq * 4 + 1], hx.y, a1);
                a2 = fma2(w[kq * 4 + 2], hy.x, a2);
                a3 = fma2(w[kq * 4 + 3], hy.y, a3);
            }
            a0 = add2(a0, a1);
            a2 = add2(a2, a3);
            a0 = add2(a0, a2);
            float z = lo32(a0) + hi32(a0);

            // ---- gate nonlinearity (one MUFU chain per lane, parallel) ----
            float v = (q == 1) ? tanhf_(z) : sigmoidf_(z);

            // ---- quad exchange via shuffles ----
            float w1 = __shfl_xor_sync(0xffffffffu, v, 1);  // q0<-g, q1<-i, q2<-o, q3<-f
            float p  = (q & 2) ? (v * c) : (v * w1);        // q2: f*c ; q0: i*g
            float y  = __shfl_xor_sync(0xffffffffu, p, 2);  // q0<->q2
            c = p + y;                                       // valid in lanes q0, q2
            float h = w1 * tanhf_(c);                        // q2: o * tanh(c)
            if (q == 2) hb[(t + s + 1) & 1][u] = h;
            __syncthreads();
        }
    }

    // ---- MLP head: out = W2 @ relu(W1 @ relu(h_T)) + b2 ; h_T in hb[0] ----
    if (j < 32) {
        float acc = 0.0f;
#pragma unroll
        for (int k = 0; k < 64; k++)
            acc = fmaf(W1[j * 64 + k], fmaxf(hb[0][k], 0.0f), acc);
        fo[j] = fmaxf(acc, 0.0f);
    }
    __syncthreads();
    if (j < 3) {
        float acc = b2v[j];
#pragma unroll
        for (int k = 0; k < 32; k++)
            acc = fmaf(W2[j * 32 + k], fo[k], acc);
        out[j] = acc;
    }
}

// ============================================================================
extern "C" void kernel_launch(void* const* d_in, const int* in_sizes, int n_in,
                              void* d_out, int out_size) {
    (void)in_sizes; (void)n_in; (void)out_size;
    const float* x    = (const float*)d_in[0];
    const float* W_ih = (const float*)d_in[1];
    const float* W_hh = (const float*)d_in[2];
    const float* b_ih = (const float*)d_in[3];
    const float* b_hh = (const float*)d_in[4];
    const float* W1   = (const float*)d_in[5];
    const float* W2   = (const float*)d_in[6];
    const float* b2   = (const float*)d_in[7];

    xz_kernel<<<T_STEPS / TS, 256>>>(x, W_ih, b_ih, b_hh);
    scan_kernel<<<1, 256>>>(W_hh, W1, W2, b2, (float*)d_out);
}

// round 3
// speedup vs baseline: 1.0952x; 1.0952x over previous
#include <cuda_runtime.h>

#define T_STEPS 65536
#define INPUT   99
#define HIDDEN  64
#define GATES   256   // 4*HIDDEN
#define TS      16    // timesteps per block in the precompute kernel

// Precomputed input projections as float2 per (t, scan-thread j):
//   even thread j=2u   owns gate rows (u      [i], u+128 [g])
//   odd  thread j=2u+1 owns gate rows (u+64   [f], u+192 [o])
//   g_xz2[t*128 + j] = (z_rowA, z_rowB)
// +8 steps of padding so the prefetch ring can read past the end harmlessly.
__device__ float g_xz[(T_STEPS + 8) * GATES];

typedef unsigned long long ull;

// ---------------- packed f32x2 helpers (Blackwell double-rate fp32) ----------------
__device__ __forceinline__ ull fma2(ull a, ull b, ull c) {
    ull d;
    asm("fma.rn.f32x2 %0, %1, %2, %3;" : "=l"(d) : "l"(a), "l"(b), "l"(c));
    return d;
}
__device__ __forceinline__ ull add2(ull a, ull b) {
    ull d;
    asm("add.rn.f32x2 %0, %1, %2;" : "=l"(d) : "l"(a), "l"(b));
    return d;
}
__device__ __forceinline__ ull pack2(float lo, float hi) {
    ull r;
    asm("mov.b64 %0, {%1, %2};" : "=l"(r) : "f"(lo), "f"(hi));
    return r;
}
__device__ __forceinline__ float lo32(ull v) { return __uint_as_float((unsigned)v); }
__device__ __forceinline__ float hi32(ull v) { return __uint_as_float((unsigned)(v >> 32)); }

// ---------------- fast-but-accurate transcendentals (MUFU, err ~1e-7) ----------------
__device__ __forceinline__ float fast_ex2(float x) {
    float y; asm("ex2.approx.f32 %0, %1;" : "=f"(y) : "f"(x)); return y;
}
__device__ __forceinline__ float fast_rcp(float x) {
    float y; asm("rcp.approx.f32 %0, %1;" : "=f"(y) : "f"(x)); return y;
}
__device__ __forceinline__ float sigmoidf_(float x) {
    return fast_rcp(1.0f + fast_ex2(-1.4426950408889634f * x));
}
__device__ __forceinline__ float tanhf_(float x) {
    // tanh(x) = 2*sigmoid(2x) - 1
    return fmaf(2.0f, fast_rcp(1.0f + fast_ex2(-2.8853900817779268f * x)), -1.0f);
}

// ============================================================================
// Kernel 1: xz[t][g] = sum_d x[t][d] * W_ih[g][d] + b_ih[g] + b_hh[g]
// Block = 256 threads (one per gate row), TS=16 timesteps per block.
// Scatters into the pair-permuted float2 layout the scan kernel wants.
// ============================================================================
__global__ void xz_kernel(const float* __restrict__ x,
                          const float* __restrict__ W_ih,
                          const float* __restrict__ b_ih,
                          const float* __restrict__ b_hh) {
    __shared__ __align__(16) float xs[INPUT * TS];  // [d][t]
    const int tid = threadIdx.x;
    const int t0  = blockIdx.x * TS;

    for (int i = tid; i < TS * INPUT; i += 256) {
        int t = i / INPUT;
        int d = i - t * INPUT;
        xs[d * TS + t] = x[(size_t)(t0 + t) * INPUT + d];
    }
    __syncthreads();

    const int g = tid;
    float bs = b_ih[g] + b_hh[g];
    float acc[TS];
#pragma unroll
    for (int t = 0; t < TS; t++) acc[t] = bs;

    const float* wrow = W_ih + g * INPUT;
#pragma unroll 3
    for (int d = 0; d < INPUT; d++) {
        float w = __ldg(wrow + d);
        const float4* xv = (const float4*)(xs + d * TS);
#pragma unroll
        for (int q = 0; q < TS / 4; q++) {
            float4 v = xv[q];
            acc[q * 4 + 0] = fmaf(w, v.x, acc[q * 4 + 0]);
            acc[q * 4 + 1] = fmaf(w, v.y, acc[q * 4 + 1]);
            acc[q * 4 + 2] = fmaf(w, v.z, acc[q * 4 + 2]);
            acc[q * 4 + 3] = fmaf(w, v.w, acc[q * 4 + 3]);
        }
    }

    // Scatter: unit u = g&63, gate gi = g>>6 (0=i,1=f,2=g,3=o)
    //   scan thread j = 2u + (gi&1), component = gi>>1
    const int u  = g & 63;
    const int gi = g >> 6;
    const int jj   = 2 * u + (gi & 1);
    const int comp = gi >> 1;
#pragma unroll
    for (int t = 0; t < TS; t++) {
        g_xz[((size_t)(t0 + t) * 128 + jj) * 2 + comp] = acc[t];
    }
}

// ============================================================================
// Kernel 2: persistent single-CTA LSTM scan + MLP head.
// 128 threads, 4 warps. Pair layout (unit u = j>>1):
//   even j: rows (u [i], u+128 [g]) ; odd j: rows (u+64 [f], u+192 [o])
// Per step (ONE __syncthreads, ONE shfl):
//   zA, zB = xz(prefetched) + W_row @ h          (64 f32x2 FMAs / thread)
//   even: p = sig(zA)*tanh(zB) = i*g ; odd: p = sig(zA)*c = f*c
//   p2 = shfl_xor(p, 1) ; c = p + p2   (identical c in both lanes)
//   odd: h[u] = sig(zB) * tanh(c) -> double-buffered SMEM ; bar
// ============================================================================
__global__ void __launch_bounds__(128, 1)
scan_kernel(const float* __restrict__ Whh,
            const float* __restrict__ W1,
            const float* __restrict__ W2,
            const float* __restrict__ b2v,
            float* __restrict__ out) {
    __shared__ __align__(16) float hb[2][HIDDEN];  // double-buffered hidden state
    __shared__ float fo[32];                       // head scratch
    const int j   = threadIdx.x;
    const int u   = j >> 1;
    const int odd = j & 1;

    const int rA = odd ? (u + 64)  : u;        // f : i
    const int rB = odd ? (u + 192) : (u + 128);// o : g

    // W_hh rows as packed f32x2 pairs (rows 256B-aligned; pairs 8B-aligned).
    ull wA[32], wB[32];
    const ull* W64 = (const ull*)Whh;
#pragma unroll
    for (int i = 0; i < 32; i++) {
        wA[i] = W64[rA * 32 + i];
        wB[i] = W64[rB * 32 + i];
    }

    if (j < HIDDEN) hb[0][j] = 0.0f;
    float c = 0.0f;  // maintained redundantly in both lanes of each pair

    // Depth-8 register prefetch ring, 1 LDG.64 per step (L2-resident buffer).
    const float2* xzp = ((const float2*)g_xz) + j;
    float2 ring[8];
#pragma unroll
    for (int p = 0; p < 8; p++) ring[p] = xzp[(size_t)p * 128];
    __syncthreads();

    for (int t = 0; t < T_STEPS; t += 8) {
#pragma unroll
        for (int s = 0; s < 8; s++) {
            float2 z = ring[s];
            ring[s] = xzp[(size_t)(t + s + 8) * 128];  // <= T+7, padded

            // ---- matvec: zA = z.x + W[rA]@h, zB = z.y + W[rB]@h ----
            const ulonglong2* h64 = (const ulonglong2*)hb[(t + s) & 1];
            ull a0 = pack2(z.x, 0.0f), a1 = 0, a2 = 0, a3 = 0;
            ull d0 = pack2(z.y, 0.0f), d1 = 0, d2 = 0, d3 = 0;
#pragma unroll
            for (int q = 0; q < 8; q++) {
                ulonglong2 hx = h64[q * 2];
                ulonglong2 hy = h64[q * 2 + 1];
                a0 = fma2(wA[q * 4 + 0], hx.x, a0);
                a1 = fma2(wA[q * 4 + 1], hx.y, a1);
                a2 = fma2(wA[q * 4 + 2], hy.x, a2);
                a3 = fma2(wA[q * 4 + 3], hy.y, a3);
                d0 = fma2(wB[q * 4 + 0], hx.x, d0);
                d1 = fma2(wB[q * 4 + 1], hx.y, d1);
                d2 = fma2(wB[q * 4 + 2], hy.x, d2);
                d3 = fma2(wB[q * 4 + 3], hy.y, d3);
            }
            a0 = add2(a0, a1); a2 = add2(a2, a3); a0 = add2(a0, a2);
            d0 = add2(d0, d1); d2 = add2(d2, d3); d0 = add2(d0, d2);
            float zA = lo32(a0) + hi32(a0);   // i (even) / f (odd)
            float zB = lo32(d0) + hi32(d0);   // g (even) / o (odd)

            // ---- gates ----
            float vA = sigmoidf_(zA);                          // i / f
            float vB = odd ? sigmoidf_(zB) : tanhf_(zB);       // o / g
            float p  = odd ? (vA * c) : (vA * vB);             // f*c / i*g
            float p2 = __shfl_xor_sync(0xffffffffu, p, 1);
            c = p + p2;                                        // same in both lanes
            float h = vB * tanhf_(c);                          // odd: o*tanh(c)
            if (odd) hb[(t + s + 1) & 1][u] = h;
            __syncthreads();
        }
    }

    // ---- MLP head: out = W2 @ relu(W1 @ relu(h_T)) + b2 ; h_T in hb[0] ----
    if (j < 32) {
        float acc = 0.0f;
#pragma unroll
        for (int k = 0; k < 64; k++)
            acc = fmaf(W1[j * 64 + k], fmaxf(hb[0][k], 0.0f), acc);
        fo[j] = fmaxf(acc, 0.0f);
    }
    __syncthreads();
    if (j < 3) {
        float acc = b2v[j];
#pragma unroll
        for (int k = 0; k < 32; k++)
            acc = fmaf(W2[j * 32 + k], fo[k], acc);
        out[j] = acc;
    }
}

// ============================================================================
extern "C" void kernel_launch(void* const* d_in, const int* in_sizes, int n_in,
                              void* d_out, int out_size) {
    (void)in_sizes; (void)n_in; (void)out_size;
    const float* x    = (const float*)d_in[0];
    const float* W_ih = (const float*)d_in[1];
    const float* W_hh = (const float*)d_in[2];
    const float* b_ih = (const float*)d_in[3];
    const float* b_hh = (const float*)d_in[4];
    const float* W1   = (const float*)d_in[5];
    const float* W2   = (const float*)d_in[6];
    const float* b2   = (const float*)d_in[7];

    xz_kernel<<<T_STEPS / TS, 256>>>(x, W_ih, b_ih, b_hh);
    scan_kernel<<<1, 128>>>(W_hh, W1, W2, b2, (float*)d_out);
}

// round 4
// speedup vs baseline: 1.2593x; 1.1498x over previous
#include <cuda_runtime.h>

#define T_STEPS 65536
#define INPUT   99
#define HIDDEN  64
#define GATES   256   // 4*HIDDEN
#define TS      16    // timesteps per block in the precompute kernel

// Precomputed input projections, packed as float2 per (t, j):
//   g_xz[(t*128 + j)*2 + 0] = xz[t][j]        (row j     : i-gate for j<64, f-gate for 64<=j<128)
//   g_xz[(t*128 + j)*2 + 1] = xz[t][j + 128]  (row j+128 : g-gate for j<64, o-gate for 64<=j<128)
// +8 steps of padding so the prefetch ring can read past the end harmlessly.
__device__ float g_xz[(T_STEPS + 8) * GATES];

typedef unsigned long long ull;

// ---------------- packed f32x2 helpers (Blackwell double-rate fp32) ----------------
__device__ __forceinline__ ull fma2(ull a, ull b, ull c) {
    ull d;
    asm("fma.rn.f32x2 %0, %1, %2, %3;" : "=l"(d) : "l"(a), "l"(b), "l"(c));
    return d;
}
__device__ __forceinline__ ull add2(ull a, ull b) {
    ull d;
    asm("add.rn.f32x2 %0, %1, %2;" : "=l"(d) : "l"(a), "l"(b));
    return d;
}
__device__ __forceinline__ ull pack2(float lo, float hi) {
    ull r;
    asm("mov.b64 %0, {%1, %2};" : "=l"(r) : "f"(lo), "f"(hi));
    return r;
}
__device__ __forceinline__ float lo32(ull v) { return __uint_as_float((unsigned)v); }
__device__ __forceinline__ float hi32(ull v) { return __uint_as_float((unsigned)(v >> 32)); }

// ---------------- fast-but-accurate transcendentals (MUFU, err ~1e-7) ----------------
__device__ __forceinline__ float fast_ex2(float x) {
    float y; asm("ex2.approx.f32 %0, %1;" : "=f"(y) : "f"(x)); return y;
}
__device__ __forceinline__ float fast_rcp(float x) {
    float y; asm("rcp.approx.f32 %0, %1;" : "=f"(y) : "f"(x)); return y;
}
__device__ __forceinline__ float sigmoidf_(float x) {
    return fast_rcp(1.0f + fast_ex2(-1.4426950408889634f * x));
}
__device__ __forceinline__ float tanhf_(float x) {
    // tanh(x) = 2*sigmoid(2x) - 1
    return fmaf(2.0f, fast_rcp(1.0f + fast_ex2(-2.8853900817779268f * x)), -1.0f);
}

// Named producer/consumer barrier: lower half arrives (non-blocking),
// upper half syncs (blocks until all 128 arrivals).
#define BAR_ARRIVE_1() asm volatile("bar.arrive 1, 128;" ::: "memory")
#define BAR_SYNC_1()   asm volatile("bar.sync 1, 128;"   ::: "memory")

// ============================================================================
// Kernel 1: xz[t][g] = sum_d x[t][d] * W_ih[g][d] + b_ih[g] + b_hh[g]
// Block = 256 threads (one per gate row), TS=16 timesteps per block.
// ============================================================================
__global__ void xz_kernel(const float* __restrict__ x,
                          const float* __restrict__ W_ih,
                          const float* __restrict__ b_ih,
                          const float* __restrict__ b_hh) {
    __shared__ __align__(16) float xs[INPUT * TS];  // [d][t]
    const int tid = threadIdx.x;
    const int t0  = blockIdx.x * TS;

    for (int i = tid; i < TS * INPUT; i += 256) {
        int t = i / INPUT;
        int d = i - t * INPUT;
        xs[d * TS + t] = x[(size_t)(t0 + t) * INPUT + d];
    }
    __syncthreads();

    const int g = tid;
    float bs = b_ih[g] + b_hh[g];
    float acc[TS];
#pragma unroll
    for (int t = 0; t < TS; t++) acc[t] = bs;

    const float* wrow = W_ih + g * INPUT;
#pragma unroll 3
    for (int d = 0; d < INPUT; d++) {
        float w = __ldg(wrow + d);
        const float4* xv = (const float4*)(xs + d * TS);
#pragma unroll
        for (int q = 0; q < TS / 4; q++) {
            float4 v = xv[q];
            acc[q * 4 + 0] = fmaf(w, v.x, acc[q * 4 + 0]);
            acc[q * 4 + 1] = fmaf(w, v.y, acc[q * 4 + 1]);
            acc[q * 4 + 2] = fmaf(w, v.z, acc[q * 4 + 2]);
            acc[q * 4 + 3] = fmaf(w, v.w, acc[q * 4 + 3]);
        }
    }

    // Scatter into the packed layout the scan kernel wants.
    const int jj   = (g < 128) ? g : (g - 128);
    const int comp = (g < 128) ? 0 : 1;
#pragma unroll
    for (int t = 0; t < TS; t++) {
        g_xz[((size_t)(t0 + t) * 128 + jj) * 2 + comp] = acc[t];
    }
}

// ============================================================================
// Kernel 2: persistent single-CTA LSTM scan + MLP head.
// 128 threads, 4 warps. Thread j owns gate rows j and j+128 (in registers).
//   j <  64 : rows (j      [i], j+128 [g])  -> computes p = sig(i)*tanh(g)
//   j >= 64 : rows (j=64+u [f], j+128 [o])  -> owns c_u; c = f*c + p; h = o*tanh(c)
// Per step: matvec (all) ; lower: p -> SMEM -> bar.arrive ;
//           upper: sigmoids (overlapped) -> bar.sync -> c,h -> SMEM ;
//           one full __syncthreads.
// ============================================================================
__global__ void __launch_bounds__(128, 1)
scan_kernel(const float* __restrict__ Whh,
            const float* __restrict__ W1,
            const float* __restrict__ W2,
            const float* __restrict__ b2v,
            float* __restrict__ out) {
    __shared__ __align__(16) float hsm[HIDDEN];
    __shared__ float psm[HIDDEN];   // p = i*g products from the lower half
    const int j = threadIdx.x;
    const bool lower = (j < 64);
    const int u = lower ? j : (j - 64);

    // W_hh rows j and j+128 as packed f32x2 pairs (rows 256B-aligned).
    ull wA[32], wB[32];
    const ull* W64 = (const ull*)Whh;
#pragma unroll
    for (int i = 0; i < 32; i++) {
        wA[i] = W64[j * 32 + i];
        wB[i] = W64[(j + 128) * 32 + i];
    }

    if (j < HIDDEN) hsm[j] = 0.0f;
    float c = 0.0f;  // live only in upper threads

    // Depth-4 register ring for xz prefetch.
    const float2* xzp = ((const float2*)g_xz) + j;
    float2 zb[4];
#pragma unroll
    for (int p = 0; p < 4; p++) zb[p] = xzp[(size_t)p * 128];
    __syncthreads();

    for (int t = 0; t < T_STEPS; t += 4) {
#pragma unroll
        for (int s = 0; s < 4; s++) {
            float2 z = zb[s];
            zb[s] = xzp[(size_t)(t + s + 4) * 128];  // reads <= T+7 (padded)

            // ---- matvec: zA = z.x + W[rowA]@h, zB = z.y + W[rowB]@h ----
            ull a0 = pack2(z.x, 0.0f), a1 = 0, a2 = 0, a3 = 0;
            ull d0 = pack2(z.y, 0.0f), d1 = 0, d2 = 0, d3 = 0;
            const ulonglong2* h64 = (const ulonglong2*)hsm;
#pragma unroll
            for (int q = 0; q < 8; q++) {
                ulonglong2 hx = h64[q * 2];
                ulonglong2 hy = h64[q * 2 + 1];
                a0 = fma2(wA[q * 4 + 0], hx.x, a0);
                a1 = fma2(wA[q * 4 + 1], hx.y, a1);
                a2 = fma2(wA[q * 4 + 2], hy.x, a2);
                a3 = fma2(wA[q * 4 + 3], hy.y, a3);
                d0 = fma2(wB[q * 4 + 0], hx.x, d0);
                d1 = fma2(wB[q * 4 + 1], hx.y, d1);
                d2 = fma2(wB[q * 4 + 2], hy.x, d2);
                d3 = fma2(wB[q * 4 + 3], hy.y, d3);
            }
            a0 = add2(a0, a1); a2 = add2(a2, a3); a0 = add2(a0, a2);
            d0 = add2(d0, d1); d2 = add2(d2, d3); d0 = add2(d0, d2);
            float zA = lo32(a0) + hi32(a0);   // i (lower) / f (upper)
            float zB = lo32(d0) + hi32(d0);   // g (lower) / o (upper)

            if (lower) {
                // p = sigmoid(i) * tanh(g), publish, signal.
                psm[u] = sigmoidf_(zA) * tanhf_(zB);
                BAR_ARRIVE_1();
            } else {
                // f,o sigmoids overlap with the lower half's chain.
                float vf = sigmoidf_(zA);
                float vo = sigmoidf_(zB);
                BAR_SYNC_1();                   // wait for p
                c = fmaf(vf, c, psm[u]);
                hsm[u] = vo * tanhf_(c);
            }
            __syncthreads();
        }
    }

    // ---- MLP head: out = W2 @ relu(W1 @ relu(h_T)) + b2 ----
    if (j < 32) {
        float acc = 0.0f;
#pragma unroll
        for (int k = 0; k < 64; k++)
            acc = fmaf(W1[j * 64 + k], fmaxf(hsm[k], 0.0f), acc);
        psm[j] = fmaxf(acc, 0.0f);
    }
    __syncthreads();
    if (j < 3) {
        float acc = b2v[j];
#pragma unroll
        for (int k = 0; k < 32; k++)
            acc = fmaf(W2[j * 32 + k], psm[k], acc);
        out[j] = acc;
    }
}

// ============================================================================
extern "C" void kernel_launch(void* const* d_in, const int* in_sizes, int n_in,
                              void* d_out, int out_size) {
    (void)in_sizes; (void)n_in; (void)out_size;
    const float* x    = (const float*)d_in[0];
    const float* W_ih = (const float*)d_in[1];
    const float* W_hh = (const float*)d_in[2];
    const float* b_ih = (const float*)d_in[3];
    const float* b_hh = (const float*)d_in[4];
    const float* W1   = (const float*)d_in[5];
    const float* W2   = (const float*)d_in[6];
    const float* b2   = (const float*)d_in[7];

    xz_kernel<<<T_STEPS / TS, 256>>>(x, W_ih, b_ih, b_hh);
    scan_kernel<<<1, 128>>>(W_hh, W1, W2, b2, (float*)d_out);
}